// round 15
// baseline (speedup 1.0000x reference)
#include <cuda_runtime.h>
#include <cuda_fp16.h>
#include <math.h>
#include <stdint.h>

#define BB   2
#define SS   2048
#define DD   1024
#define HH   16
#define DKH  64
#define DFF  4096
#define MM   (BB*SS)     // 4096 rows total
#define EPSV 1e-5f

// ---------------- scratch (device globals: allocation-free) ----------------
__device__ __half g_xn  [MM*DD];
__device__ __half g_qkv [MM*3*DD];
__device__ __half g_att [MM*DD];
__device__ float  g_x1  [MM*DD];
__device__ __half g_xn2 [MM*DD];
__device__ __half g_ff  [MM*DFF];
__device__ __half g_wqkv[3*DD*DD];
__device__ __half g_woc [DD*DD];
__device__ __half g_w1c [DFF*DD];
__device__ __half g_w2c [DD*DFF];

// ---------------- small helpers ----------------
__device__ __forceinline__ float gelu_erf(float x) {
    return 0.5f * x * (1.0f + erff(x * 0.70710678118654752f));
}
__device__ __forceinline__ uint32_t pack_h2(float lo, float hi) {
    uint32_t r;
    asm("{ .reg .f16 l, h;\n\t"
        "cvt.rn.f16.f32 l, %1;\n\t"
        "cvt.rn.f16.f32 h, %2;\n\t"
        "mov.b32 %0, {l, h}; }"
        : "=r"(r) : "f"(lo), "f"(hi));
    return r;
}
__device__ __forceinline__ uint32_t ex2_h2(uint32_t x) {
    uint32_t r;
    asm("ex2.approx.f16x2 %0, %1;" : "=r"(r) : "r"(x));
    return r;
}
__device__ __forceinline__ float ex2f(float x) {
    float r;
    asm("ex2.approx.ftz.f32 %0, %1;" : "=f"(r) : "f"(x));
    return r;
}
__device__ __forceinline__ uint32_t smem_u32(const void* p) {
    uint32_t a;
    asm("{ .reg .u64 t; cvta.to.shared.u64 t, %1; cvt.u32.u64 %0, t; }"
        : "=r"(a) : "l"(p));
    return a;
}
__device__ __forceinline__ void cp16(uint32_t smaddr, const void* gptr) {
    asm volatile("cp.async.cg.shared.global [%0], [%1], 16;"
                 :: "r"(smaddr), "l"(gptr) : "memory");
}
#define CP_COMMIT() asm volatile("cp.async.commit_group;" ::: "memory")

__device__ __forceinline__ void ldsm4(uint32_t& r0, uint32_t& r1,
                                      uint32_t& r2, uint32_t& r3, uint32_t a) {
    asm volatile("ldmatrix.sync.aligned.m8n8.x4.shared.b16 {%0,%1,%2,%3}, [%4];"
                 : "=r"(r0), "=r"(r1), "=r"(r2), "=r"(r3) : "r"(a));
}
__device__ __forceinline__ void ldsm4t(uint32_t& r0, uint32_t& r1,
                                       uint32_t& r2, uint32_t& r3, uint32_t a) {
    asm volatile("ldmatrix.sync.aligned.m8n8.x4.trans.shared.b16 {%0,%1,%2,%3}, [%4];"
                 : "=r"(r0), "=r"(r1), "=r"(r2), "=r"(r3) : "r"(a));
}
__device__ __forceinline__ void mma_f16(float c[4],
                                        uint32_t a0, uint32_t a1, uint32_t a2, uint32_t a3,
                                        uint32_t b0, uint32_t b1) {
    asm volatile(
        "mma.sync.aligned.m16n8k16.row.col.f32.f16.f16.f32 "
        "{%0,%1,%2,%3},{%4,%5,%6,%7},{%8,%9},{%0,%1,%2,%3};"
        : "+f"(c[0]), "+f"(c[1]), "+f"(c[2]), "+f"(c[3])
        : "r"(a0), "r"(a1), "r"(a2), "r"(a3), "r"(b0), "r"(b1));
}

// ---------------- RMSNorm (fp32 in, fp16 out) ----------------
__global__ void rmsnorm_kernel(const float* __restrict__ x,
                               const float* __restrict__ g,
                               __half* __restrict__ out) {
    int row = blockIdx.x;
    int t = threadIdx.x;
    float4 v = ((const float4*)(x + (size_t)row * DD))[t];
    float s = v.x*v.x + v.y*v.y + v.z*v.z + v.w*v.w;
    #pragma unroll
    for (int o = 16; o; o >>= 1) s += __shfl_xor_sync(0xffffffffu, s, o);
    __shared__ float ws[8];
    __shared__ float tot;
    if ((t & 31) == 0) ws[t >> 5] = s;
    __syncthreads();
    if (t == 0) {
        float z = 0.f;
        #pragma unroll
        for (int i = 0; i < 8; i++) z += ws[i];
        tot = rsqrtf(z * (1.0f / DD) + EPSV);
    }
    __syncthreads();
    float rn = tot;
    float4 gv = ((const float4*)g)[t];
    uint32_t* op = (uint32_t*)(out + (size_t)row * DD) + t * 2;
    op[0] = pack_h2(v.x*rn*gv.x, v.y*rn*gv.y);
    op[1] = pack_h2(v.z*rn*gv.z, v.w*rn*gv.w);
}

// ---------------- all weights fp32 -> fp16 in one kernel ----------------
#define W_QKV (3*DD*DD/4)
#define W_O   (DD*DD/4)
#define W_1   (DFF*DD/4)
#define W_2   (DD*DFF/4)
__global__ void cvt_all(const float* __restrict__ wq, const float* __restrict__ wk,
                        const float* __restrict__ wv, const float* __restrict__ wo,
                        const float* __restrict__ w1, const float* __restrict__ w2,
                        __half* __restrict__ dqkv, __half* __restrict__ dwo,
                        __half* __restrict__ dw1, __half* __restrict__ dw2) {
    int total = W_QKV + W_O + W_1 + W_2;
    #pragma unroll 2
    for (int i = blockIdx.x * blockDim.x + threadIdx.x; i < total;
         i += gridDim.x * blockDim.x) {
        const float* src; __half* dst; int j = i;
        if (j < W_QKV) {
            int seg = j / (DD*DD/4), off = j % (DD*DD/4);
            src = (seg == 0 ? wq : seg == 1 ? wk : wv) + (size_t)off * 4;
            dst = dqkv + (size_t)j * 4;
        } else if ((j -= W_QKV) < W_O) {
            src = wo + (size_t)j * 4; dst = dwo + (size_t)j * 4;
        } else if ((j -= W_O) < W_1) {
            src = w1 + (size_t)j * 4; dst = dw1 + (size_t)j * 4;
        } else {
            j -= W_1;
            src = w2 + (size_t)j * 4; dst = dw2 + (size_t)j * 4;
        }
        float4 v = *(const float4*)src;
        ((uint32_t*)dst)[0] = pack_h2(v.x, v.y);
        ((uint32_t*)dst)[1] = pack_h2(v.z, v.w);
    }
}

// ---------------- fp16 mma GEMM: C[M,N] = A[M,K]*B[N,K]^T (+epilogue) ----------------
#define GS      3
#define KSLAB   64
#define PITCHB  144
#define STAGE_B (128*PITCHB)
#define PAIR_B  (2*STAGE_B)
#define GSMEM   (GS*PAIR_B)

// EPI: 0 = fp16 out, 1 = fp32 out + fp32 residual, 2 = fp16 out gelu
template<int EPI>
__global__ void __launch_bounds__(256, 2)
gemm_h(const __half* __restrict__ A, const __half* __restrict__ B,
       const float* __restrict__ R, void* __restrict__ Cout,
       int M, int N, int K) {
    extern __shared__ __align__(16) char smp[];
    uint32_t sb = smem_u32(smp);
    int tid = threadIdx.x;
    int wid = tid >> 5, lane = tid & 31;
    int warp_m = (wid & 1) * 64;
    int warp_n = (wid >> 1) * 32;
    int tg = lane >> 2, tq = lane & 3;
    int bm = blockIdx.y * 128, bn = blockIdx.x * 128;

    int li = lane & 7, ls = lane >> 3;
    uint32_t aoffs = (uint32_t)((warp_m + li + (ls & 1) * 8) * PITCHB + (ls >> 1) * 16);
    uint32_t boffs = (uint32_t)((warp_n + li + (ls >> 1) * 8) * PITCHB + (ls & 1) * 16);

    int lrow[4], lchn[4];
    #pragma unroll
    for (int p = 0; p < 4; p++) {
        int idx = tid + p * 256;
        lrow[p] = idx >> 3;
        lchn[p] = idx & 7;
    }

    float acc[4][4][4];
    #pragma unroll
    for (int i = 0; i < 4; i++)
        #pragma unroll
        for (int j = 0; j < 4; j++)
            #pragma unroll
            for (int q = 0; q < 4; q++) acc[i][j][q] = 0.f;

    int NS = K / KSLAB;

    #pragma unroll
    for (int p = 0; p < GS - 1; p++) {
        uint32_t sa = sb + p * PAIR_B;
        uint32_t sbb = sa + STAGE_B;
        #pragma unroll
        for (int i = 0; i < 4; i++) {
            cp16(sa  + lrow[i]*PITCHB + lchn[i]*16,
                 A + (size_t)(bm + lrow[i]) * K + p * KSLAB + lchn[i]*8);
            cp16(sbb + lrow[i]*PITCHB + lchn[i]*16,
                 B + (size_t)(bn + lrow[i]) * K + p * KSLAB + lchn[i]*8);
        }
        CP_COMMIT();
    }

    // double-buffered fragments across kt steps
    uint32_t af[2][4][4], bf[2][4][2];

    for (int slab = 0; slab < NS; slab++) {
        asm volatile("cp.async.wait_group %0;" :: "n"(GS - 2) : "memory");
        __syncthreads();

        int t = slab + GS - 1;
        if (t < NS) {
            uint32_t sa = sb + (t % GS) * PAIR_B;
            uint32_t sbb = sa + STAGE_B;
            #pragma unroll
            for (int i = 0; i < 4; i++) {
                cp16(sa  + lrow[i]*PITCHB + lchn[i]*16,
                     A + (size_t)(bm + lrow[i]) * K + t * KSLAB + lchn[i]*8);
                cp16(sbb + lrow[i]*PITCHB + lchn[i]*16,
                     B + (size_t)(bn + lrow[i]) * K + t * KSLAB + lchn[i]*8);
            }
        }
        CP_COMMIT();

        uint32_t Asm = sb + (slab % GS) * PAIR_B;
        uint32_t Bsm = Asm + STAGE_B;

        // prologue frags for kt=0 into buffer 0
        #pragma unroll
        for (int mt = 0; mt < 4; mt++)
            ldsm4(af[0][mt][0], af[0][mt][1], af[0][mt][2], af[0][mt][3],
                  Asm + aoffs + mt * (16 * PITCHB));
        #pragma unroll
        for (int p = 0; p < 2; p++) {
            uint32_t r0, r1, r2, r3;
            ldsm4(r0, r1, r2, r3, Bsm + boffs + p * (16 * PITCHB));
            bf[0][p*2][0]   = r0; bf[0][p*2][1]   = r1;
            bf[0][p*2+1][0] = r2; bf[0][p*2+1][1] = r3;
        }

        #pragma unroll
        for (int kt = 0; kt < 4; kt++) {
            int cur = kt & 1, nxt = cur ^ 1;
            if (kt < 3) {
                // issue next kt's ldsm before this kt's mma block
                #pragma unroll
                for (int mt = 0; mt < 4; mt++)
                    ldsm4(af[nxt][mt][0], af[nxt][mt][1], af[nxt][mt][2], af[nxt][mt][3],
                          Asm + aoffs + mt * (16 * PITCHB) + (kt + 1) * 32);
                #pragma unroll
                for (int p = 0; p < 2; p++) {
                    uint32_t r0, r1, r2, r3;
                    ldsm4(r0, r1, r2, r3,
                          Bsm + boffs + p * (16 * PITCHB) + (kt + 1) * 32);
                    bf[nxt][p*2][0]   = r0; bf[nxt][p*2][1]   = r1;
                    bf[nxt][p*2+1][0] = r2; bf[nxt][p*2+1][1] = r3;
                }
            }
            #pragma unroll
            for (int mt = 0; mt < 4; mt++)
                #pragma unroll
                for (int nt = 0; nt < 4; nt++)
                    mma_f16(acc[mt][nt],
                            af[cur][mt][0], af[cur][mt][1], af[cur][mt][2], af[cur][mt][3],
                            bf[cur][nt][0], bf[cur][nt][1]);
        }
    }

    #pragma unroll
    for (int mt = 0; mt < 4; mt++) {
        #pragma unroll
        for (int nt = 0; nt < 4; nt++) {
            int r0o = bm + warp_m + mt * 16 + tg;
            int r1o = r0o + 8;
            int c = bn + warp_n + nt * 8 + tq * 2;
            float2 v0 = make_float2(acc[mt][nt][0], acc[mt][nt][1]);
            float2 v1 = make_float2(acc[mt][nt][2], acc[mt][nt][3]);
            if (EPI == 1) {
                float* Cf = (float*)Cout;
                float2 rv0 = *(const float2*)(R + (size_t)r0o * N + c);
                float2 rv1 = *(const float2*)(R + (size_t)r1o * N + c);
                v0.x += rv0.x; v0.y += rv0.y;
                v1.x += rv1.x; v1.y += rv1.y;
                *(float2*)(Cf + (size_t)r0o * N + c) = v0;
                *(float2*)(Cf + (size_t)r1o * N + c) = v1;
            } else {
                if (EPI == 2) {
                    v0.x = gelu_erf(v0.x); v0.y = gelu_erf(v0.y);
                    v1.x = gelu_erf(v1.x); v1.y = gelu_erf(v1.y);
                }
                __half* Ch = (__half*)Cout;
                *(uint32_t*)(Ch + (size_t)r0o * N + c) = pack_h2(v0.x, v0.y);
                *(uint32_t*)(Ch + (size_t)r1o * N + c) = pack_h2(v1.x, v1.y);
            }
        }
    }
}

// ---------------- fp16 flash attention (causal, dk=64, log2-softmax, cp.async) ----------------
#define FPH   72
#define FPHB  (FPH*2)           // 144
#define QBYTES (64*FPHB)        // 9216
#define KVPAIR (2*QBYTES)       // 18432 per stage
#define FSMH  (QBYTES + 2*KVPAIR)   // 46080
#define QSCAL 0.18033688011112042f  // 0.125 * log2(e)

__global__ void __launch_bounds__(128)
flash_h(const __half* __restrict__ q, const __half* __restrict__ k,
        const __half* __restrict__ v, __half* __restrict__ o, int ldq) {
    extern __shared__ __align__(16) char smc[];
    uint32_t sbase = smem_u32(smc);
    __half* Qh = (__half*)smc;

    int qi = gridDim.x - 1 - blockIdx.x;   // heavy tiles first (neutral, harmless)
    int bh = blockIdx.y;
    int b = bh >> 4, h = bh & 15;
    const __half* qp    = q + ((size_t)(b*SS + qi*64)) * ldq + h*DKH;
    const __half* kbase = k + (size_t)b * SS * ldq + h*DKH;
    const __half* vbase = v + (size_t)b * SS * ldq + h*DKH;

    int tid = threadIdx.x;
    int w = tid >> 5, lane = tid & 31;
    int tg = lane >> 2, tq = lane & 3;
    int li = lane & 7, ls = lane >> 3;

    int lr = tid >> 2, lch = tid & 3;

    uint32_t aoffs = (uint32_t)((w*16 + li + (ls & 1) * 8) * FPHB + (ls >> 1) * 16);
    uint32_t boffs = (uint32_t)((li + (ls >> 1) * 8) * FPHB + (ls & 1) * 16);
    uint32_t voffs = (uint32_t)((li + (ls & 1) * 8) * FPHB + (ls >> 1) * 16);

    #pragma unroll
    for (int i = 0; i < 2; i++) {
        int r = lr + i * 32;
        #pragma unroll
        for (int jc = 0; jc < 2; jc++) {
            int c = (lch + jc * 4) * 8;
            const __half2* qg = (const __half2*)(qp + (size_t)r * ldq + c);
            uint32_t* qs = (uint32_t*)(Qh + r * FPH + c);
            #pragma unroll
            for (int j = 0; j < 4; j++) {
                float2 f = __half22float2(qg[j]);
                qs[j] = pack_h2(f.x * QSCAL, f.y * QSCAL);
            }
        }
    }
    __syncthreads();
    uint32_t qf[4][4];
    #pragma unroll
    for (int kt = 0; kt < 4; kt++)
        ldsm4(qf[kt][0], qf[kt][1], qf[kt][2], qf[kt][3], sbase + aoffs + kt * 32);

    {
        uint32_t Ks0 = sbase + QBYTES;
        uint32_t Vs0 = Ks0 + QBYTES;
        #pragma unroll
        for (int i = 0; i < 2; i++) {
            int r = lr + i * 32;
            #pragma unroll
            for (int jc = 0; jc < 2; jc++) {
                int c = lch + jc * 4;
                cp16(Ks0 + r*FPHB + c*16, kbase + (size_t)r * ldq + c*8);
                cp16(Vs0 + r*FPHB + c*16, vbase + (size_t)r * ldq + c*8);
            }
        }
        CP_COMMIT();
    }

    float ofrag[8][4];
    #pragma unroll
    for (int nt = 0; nt < 8; nt++)
        #pragma unroll
        for (int j = 0; j < 4; j++) ofrag[nt][j] = 0.f;
    float mrow0 = -INFINITY, mrow1 = -INFINITY, lrow0 = 0.f, lrow1 = 0.f;
    const uint32_t ONE2 = 0x3C003C00u;

    for (int jt = 0; jt <= qi; jt++) {
        __syncthreads();
        if (jt < qi) {
            int nt_ = jt + 1;
            uint32_t Ksn = sbase + QBYTES + ((nt_) & 1) * KVPAIR;
            uint32_t Vsn = Ksn + QBYTES;
            #pragma unroll
            for (int i = 0; i < 2; i++) {
                int r = lr + i * 32;
                #pragma unroll
                for (int jc = 0; jc < 2; jc++) {
                    int c = lch + jc * 4;
                    cp16(Ksn + r*FPHB + c*16, kbase + (size_t)(nt_*64 + r) * ldq + c*8);
                    cp16(Vsn + r*FPHB + c*16, vbase + (size_t)(nt_*64 + r) * ldq + c*8);
                }
            }
            CP_COMMIT();
            asm volatile("cp.async.wait_group 1;" ::: "memory");
        } else {
            asm volatile("cp.async.wait_group 0;" ::: "memory");
        }
        __syncthreads();

        uint32_t Ksm = sbase + QBYTES + (jt & 1) * KVPAIR;
        uint32_t Vsm = Ksm + QBYTES;

        float s[8][4];
        #pragma unroll
        for (int nt = 0; nt < 8; nt++)
            #pragma unroll
            for (int j = 0; j < 4; j++) s[nt][j] = 0.f;
        #pragma unroll
        for (int kt = 0; kt < 4; kt++) {
            #pragma unroll
            for (int nb = 0; nb < 4; nb++) {
                uint32_t r0, r1, r2, r3;
                ldsm4(r0, r1, r2, r3, Ksm + boffs + nb * (16 * FPHB) + kt * 32);
                mma_f16(s[nb*2],   qf[kt][0], qf[kt][1], qf[kt][2], qf[kt][3], r0, r1);
                mma_f16(s[nb*2+1], qf[kt][0], qf[kt][1], qf[kt][2], qf[kt][3], r2, r3);
            }
        }

        if (jt == qi) {
            int r0 = w*16 + tg, r1 = r0 + 8;
            #pragma unroll
            for (int nt = 0; nt < 8; nt++) {
                int c0 = nt*8 + 2*tq, c1 = c0 + 1;
                if (c0 > r0) s[nt][0] = -INFINITY;
                if (c1 > r0) s[nt][1] = -INFINITY;
                if (c0 > r1) s[nt][2] = -INFINITY;
                if (c1 > r1) s[nt][3] = -INFINITY;
            }
        }

        float m0 = -INFINITY, m1 = -INFINITY;
        #pragma unroll
        for (int nt = 0; nt < 8; nt++) {
            m0 = fmaxf(m0, fmaxf(s[nt][0], s[nt][1]));
            m1 = fmaxf(m1, fmaxf(s[nt][2], s[nt][3]));
        }
        m0 = fmaxf(m0, __shfl_xor_sync(0xffffffffu, m0, 1));
        m0 = fmaxf(m0, __shfl_xor_sync(0xffffffffu, m0, 2));
        m1 = fmaxf(m1, __shfl_xor_sync(0xffffffffu, m1, 1));
        m1 = fmaxf(m1, __shfl_xor_sync(0xffffffffu, m1, 2));

        float mn0 = fmaxf(mrow0, m0), mn1 = fmaxf(mrow1, m1);
        float corr0 = ex2f(mrow0 - mn0), corr1 = ex2f(mrow1 - mn1);
        mrow0 = mn0; mrow1 = mn1;

        uint32_t pk[4][4];
        #pragma unroll
        for (int nt = 0; nt < 8; nt++) {
            int kt = nt >> 1, hi = nt & 1;
            pk[kt][hi*2]     = ex2_h2(pack_h2(s[nt][0] - mn0, s[nt][1] - mn0));
            pk[kt][hi*2 + 1] = ex2_h2(pack_h2(s[nt][2] - mn1, s[nt][3] - mn1));
            ofrag[nt][0] *= corr0; ofrag[nt][1] *= corr0;
            ofrag[nt][2] *= corr1; ofrag[nt][3] *= corr1;
        }

        float rsf[4] = {0.f, 0.f, 0.f, 0.f};
        #pragma unroll
        for (int kt = 0; kt < 4; kt++)
            mma_f16(rsf, pk[kt][0], pk[kt][1], pk[kt][2], pk[kt][3], ONE2, ONE2);
        lrow0 = lrow0 * corr0 + rsf[0];
        lrow1 = lrow1 * corr1 + rsf[2];

        #pragma unroll
        for (int kt = 0; kt < 4; kt++) {
            #pragma unroll
            for (int nb = 0; nb < 4; nb++) {
                uint32_t r0, r1, r2, r3;
                ldsm4t(r0, r1, r2, r3,
                       Vsm + voffs + kt * (16 * FPHB) + nb * 32);
                mma_f16(ofrag[nb*2],   pk[kt][0], pk[kt][1], pk[kt][2], pk[kt][3], r0, r1);
                mma_f16(ofrag[nb*2+1], pk[kt][0], pk[kt][1], pk[kt][2], pk[kt][3], r2, r3);
            }
        }
    }

    float inv0 = 1.0f / lrow0, inv1 = 1.0f / lrow1;
    int r0 = qi*64 + w*16 + tg, r1 = r0 + 8;
    __half* op = o + (size_t)(b*SS) * DD + h*DKH;
    #pragma unroll
    for (int nt = 0; nt < 8; nt++) {
        int c = nt*8 + 2*tq;
        *(uint32_t*)(op + (size_t)r0 * DD + c) =
            pack_h2(ofrag[nt][0]*inv0, ofrag[nt][1]*inv0);
        *(uint32_t*)(op + (size_t)r1 * DD + c) =
            pack_h2(ofrag[nt][2]*inv1, ofrag[nt][3]*inv1);
    }
}

// ---------------- launch ----------------
extern "C" void kernel_launch(void* const* d_in, const int* in_sizes, int n_in,
                              void* d_out, int out_size) {
    const float* x  = (const float*)d_in[0];
    const float* g1 = (const float*)d_in[1];
    const float* g2 = (const float*)d_in[2];
    const float* wq = (const float*)d_in[3];
    const float* wk = (const float*)d_in[4];
    const float* wv = (const float*)d_in[5];
    const float* wo = (const float*)d_in[6];
    const float* w1 = (const float*)d_in[7];
    const float* w2 = (const float*)d_in[8];
    float* out = (float*)d_out;

    __half *xn, *qkv, *att, *xn2, *ff, *wqkvc, *woc, *w1c, *w2c;
    float* x1;
    cudaGetSymbolAddress((void**)&xn,    g_xn);
    cudaGetSymbolAddress((void**)&qkv,   g_qkv);
    cudaGetSymbolAddress((void**)&att,   g_att);
    cudaGetSymbolAddress((void**)&x1,    g_x1);
    cudaGetSymbolAddress((void**)&xn2,   g_xn2);
    cudaGetSymbolAddress((void**)&ff,    g_ff);
    cudaGetSymbolAddress((void**)&wqkvc, g_wqkv);
    cudaGetSymbolAddress((void**)&woc,   g_woc);
    cudaGetSymbolAddress((void**)&w1c,   g_w1c);
    cudaGetSymbolAddress((void**)&w2c,   g_w2c);

    cudaFuncSetAttribute(flash_h,
                         cudaFuncAttributeMaxDynamicSharedMemorySize, FSMH);
    cudaFuncSetAttribute(gemm_h<0>,
                         cudaFuncAttributeMaxDynamicSharedMemorySize, GSMEM);
    cudaFuncSetAttribute(gemm_h<1>,
                         cudaFuncAttributeMaxDynamicSharedMemorySize, GSMEM);
    cudaFuncSetAttribute(gemm_h<2>,
                         cudaFuncAttributeMaxDynamicSharedMemorySize, GSMEM);

    cvt_all<<<1024, 256>>>(wq, wk, wv, wo, w1, w2, wqkvc, woc, w1c, w2c);

    // 1. xn = rmsnorm(x, g1)
    rmsnorm_kernel<<<MM, 256>>>(x, g1, xn);
    // 2. fused QKV
    gemm_h<0><<<dim3(3*DD/128, MM/128), 256, GSMEM>>>(xn, wqkvc, nullptr, qkv,
                                                      MM, 3*DD, DD);
    // 3. causal flash attention
    flash_h<<<dim3(SS/64, BB*HH), 128, FSMH>>>(qkv, qkv + DD, qkv + 2*DD, att, 3*DD);
    // 4. x1 = x + att @ wo^T
    gemm_h<1><<<dim3(DD/128, MM/128), 256, GSMEM>>>(att, woc, x, x1, MM, DD, DD);
    // 5. xn2 = rmsnorm(x1, g2)
    rmsnorm_kernel<<<MM, 256>>>(x1, g2, xn2);
    // 6. ff = gelu(xn2 @ w1^T)
    gemm_h<2><<<dim3(DFF/128, MM/128), 256, GSMEM>>>(xn2, w1c, nullptr, ff,
                                                     MM, DFF, DD);
    // 7. out = x1 + ff @ w2^T
    gemm_h<1><<<dim3(DD/128, MM/128), 256, GSMEM>>>(ff, w2c, x1, out, MM, DD, DFF);
}

// round 16
// speedup vs baseline: 1.0384x; 1.0384x over previous
#include <cuda_runtime.h>
#include <cuda_fp16.h>
#include <math.h>
#include <stdint.h>

#define BB   2
#define SS   2048
#define DD   1024
#define HH   16
#define DKH  64
#define DFF  4096
#define MM   (BB*SS)     // 4096 rows total
#define EPSV 1e-5f

// ---------------- scratch (device globals: allocation-free) ----------------
__device__ __half g_xn  [MM*DD];
__device__ __half g_qkv [MM*3*DD];
__device__ __half g_att [MM*DD];
__device__ float  g_x1  [MM*DD];
__device__ __half g_xn2 [MM*DD];
__device__ __half g_ff  [MM*DFF];
__device__ __half g_wqkv[3*DD*DD];
__device__ __half g_woc [DD*DD];
__device__ __half g_w1c [DFF*DD];
__device__ __half g_w2c [DD*DFF];

// ---------------- small helpers ----------------
__device__ __forceinline__ float gelu_erf(float x) {
    return 0.5f * x * (1.0f + erff(x * 0.70710678118654752f));
}
__device__ __forceinline__ uint32_t pack_h2(float lo, float hi) {
    uint32_t r;
    asm("{ .reg .f16 l, h;\n\t"
        "cvt.rn.f16.f32 l, %1;\n\t"
        "cvt.rn.f16.f32 h, %2;\n\t"
        "mov.b32 %0, {l, h}; }"
        : "=r"(r) : "f"(lo), "f"(hi));
    return r;
}
__device__ __forceinline__ uint32_t ex2_h2(uint32_t x) {
    uint32_t r;
    asm("ex2.approx.f16x2 %0, %1;" : "=r"(r) : "r"(x));
    return r;
}
__device__ __forceinline__ float ex2f(float x) {
    float r;
    asm("ex2.approx.ftz.f32 %0, %1;" : "=f"(r) : "f"(x));
    return r;
}
__device__ __forceinline__ uint32_t smem_u32(const void* p) {
    uint32_t a;
    asm("{ .reg .u64 t; cvta.to.shared.u64 t, %1; cvt.u32.u64 %0, t; }"
        : "=r"(a) : "l"(p));
    return a;
}
__device__ __forceinline__ void cp16(uint32_t smaddr, const void* gptr) {
    asm volatile("cp.async.cg.shared.global [%0], [%1], 16;"
                 :: "r"(smaddr), "l"(gptr) : "memory");
}
#define CP_COMMIT() asm volatile("cp.async.commit_group;" ::: "memory")

__device__ __forceinline__ void ldsm4(uint32_t& r0, uint32_t& r1,
                                      uint32_t& r2, uint32_t& r3, uint32_t a) {
    asm volatile("ldmatrix.sync.aligned.m8n8.x4.shared.b16 {%0,%1,%2,%3}, [%4];"
                 : "=r"(r0), "=r"(r1), "=r"(r2), "=r"(r3) : "r"(a));
}
__device__ __forceinline__ void ldsm4t(uint32_t& r0, uint32_t& r1,
                                       uint32_t& r2, uint32_t& r3, uint32_t a) {
    asm volatile("ldmatrix.sync.aligned.m8n8.x4.trans.shared.b16 {%0,%1,%2,%3}, [%4];"
                 : "=r"(r0), "=r"(r1), "=r"(r2), "=r"(r3) : "r"(a));
}
__device__ __forceinline__ void mma_f16(float c[4],
                                        uint32_t a0, uint32_t a1, uint32_t a2, uint32_t a3,
                                        uint32_t b0, uint32_t b1) {
    asm volatile(
        "mma.sync.aligned.m16n8k16.row.col.f32.f16.f16.f32 "
        "{%0,%1,%2,%3},{%4,%5,%6,%7},{%8,%9},{%0,%1,%2,%3};"
        : "+f"(c[0]), "+f"(c[1]), "+f"(c[2]), "+f"(c[3])
        : "r"(a0), "r"(a1), "r"(a2), "r"(a3), "r"(b0), "r"(b1));
}

// ---------------- RMSNorm: warp-per-row, 8 rows/block, shuffle-only ----------------
__global__ void rmsnorm_kernel(const float* __restrict__ x,
                               const float* __restrict__ g,
                               __half* __restrict__ out) {
    int w = threadIdx.x >> 5, lane = threadIdx.x & 31;
    int row = blockIdx.x * 8 + w;
    const float4* xp = (const float4*)(x + (size_t)row * DD);
    float4 v[8];
    float s = 0.f;
    #pragma unroll
    for (int i = 0; i < 8; i++) {
        v[i] = xp[lane + i * 32];
        s += v[i].x*v[i].x + v[i].y*v[i].y + v[i].z*v[i].z + v[i].w*v[i].w;
    }
    #pragma unroll
    for (int o = 16; o; o >>= 1) s += __shfl_xor_sync(0xffffffffu, s, o);
    float rn = rsqrtf(s * (1.0f / DD) + EPSV);
    const float4* gp = (const float4*)g;
    uint32_t* op = (uint32_t*)(out + (size_t)row * DD);
    #pragma unroll
    for (int i = 0; i < 8; i++) {
        float4 gv = gp[lane + i * 32];
        int b = (lane + i * 32) * 2;
        op[b]     = pack_h2(v[i].x*rn*gv.x, v[i].y*rn*gv.y);
        op[b + 1] = pack_h2(v[i].z*rn*gv.z, v[i].w*rn*gv.w);
    }
}

// ---------------- all weights fp32 -> fp16 in one kernel ----------------
#define W_QKV (3*DD*DD/4)
#define W_O   (DD*DD/4)
#define W_1   (DFF*DD/4)
#define W_2   (DD*DFF/4)
__global__ void cvt_all(const float* __restrict__ wq, const float* __restrict__ wk,
                        const float* __restrict__ wv, const float* __restrict__ wo,
                        const float* __restrict__ w1, const float* __restrict__ w2,
                        __half* __restrict__ dqkv, __half* __restrict__ dwo,
                        __half* __restrict__ dw1, __half* __restrict__ dw2) {
    int total = W_QKV + W_O + W_1 + W_2;
    for (int i = blockIdx.x * blockDim.x + threadIdx.x; i < total;
         i += gridDim.x * blockDim.x) {
        const float* src; __half* dst; int j = i;
        if (j < W_QKV) {
            int seg = j / (DD*DD/4), off = j % (DD*DD/4);
            src = (seg == 0 ? wq : seg == 1 ? wk : wv) + (size_t)off * 4;
            dst = dqkv + (size_t)j * 4;
        } else if ((j -= W_QKV) < W_O) {
            src = wo + (size_t)j * 4; dst = dwo + (size_t)j * 4;
        } else if ((j -= W_O) < W_1) {
            src = w1 + (size_t)j * 4; dst = dw1 + (size_t)j * 4;
        } else {
            j -= W_1;
            src = w2 + (size_t)j * 4; dst = dw2 + (size_t)j * 4;
        }
        float4 v = *(const float4*)src;
        ((uint32_t*)dst)[0] = pack_h2(v.x, v.y);
        ((uint32_t*)dst)[1] = pack_h2(v.z, v.w);
    }
}

// ---------------- fp16 mma GEMM: C[M,N] = A[M,K]*B[N,K]^T (+epilogue) ----------------
#define GS      3
#define KSLAB   64
#define PITCHB  144
#define STAGE_B (128*PITCHB)
#define PAIR_B  (2*STAGE_B)
#define GSMEM   (GS*PAIR_B)

// EPI: 0 = fp16 out, 1 = fp32 out + fp32 residual, 2 = fp16 out gelu
template<int EPI>
__global__ void __launch_bounds__(256, 2)
gemm_h(const __half* __restrict__ A, const __half* __restrict__ B,
       const float* __restrict__ R, void* __restrict__ Cout,
       int M, int N, int K) {
    extern __shared__ __align__(16) char smp[];
    uint32_t sb = smem_u32(smp);
    int tid = threadIdx.x;
    int wid = tid >> 5, lane = tid & 31;
    int warp_m = (wid & 1) * 64;
    int warp_n = (wid >> 1) * 32;
    int tg = lane >> 2, tq = lane & 3;
    int bm = blockIdx.y * 128, bn = blockIdx.x * 128;

    int li = lane & 7, ls = lane >> 3;
    uint32_t aoffs = (uint32_t)((warp_m + li + (ls & 1) * 8) * PITCHB + (ls >> 1) * 16);
    uint32_t boffs = (uint32_t)((warp_n + li + (ls >> 1) * 8) * PITCHB + (ls & 1) * 16);

    int lrow[4], lchn[4];
    #pragma unroll
    for (int p = 0; p < 4; p++) {
        int idx = tid + p * 256;
        lrow[p] = idx >> 3;
        lchn[p] = idx & 7;
    }

    float acc[4][4][4];
    #pragma unroll
    for (int i = 0; i < 4; i++)
        #pragma unroll
        for (int j = 0; j < 4; j++)
            #pragma unroll
            for (int q = 0; q < 4; q++) acc[i][j][q] = 0.f;

    int NS = K / KSLAB;

    #pragma unroll
    for (int p = 0; p < GS - 1; p++) {
        uint32_t sa = sb + p * PAIR_B;
        uint32_t sbb = sa + STAGE_B;
        #pragma unroll
        for (int i = 0; i < 4; i++) {
            cp16(sa  + lrow[i]*PITCHB + lchn[i]*16,
                 A + (size_t)(bm + lrow[i]) * K + p * KSLAB + lchn[i]*8);
            cp16(sbb + lrow[i]*PITCHB + lchn[i]*16,
                 B + (size_t)(bn + lrow[i]) * K + p * KSLAB + lchn[i]*8);
        }
        CP_COMMIT();
    }

    for (int slab = 0; slab < NS; slab++) {
        asm volatile("cp.async.wait_group %0;" :: "n"(GS - 2) : "memory");
        __syncthreads();

        int t = slab + GS - 1;
        if (t < NS) {
            uint32_t sa = sb + (t % GS) * PAIR_B;
            uint32_t sbb = sa + STAGE_B;
            #pragma unroll
            for (int i = 0; i < 4; i++) {
                cp16(sa  + lrow[i]*PITCHB + lchn[i]*16,
                     A + (size_t)(bm + lrow[i]) * K + t * KSLAB + lchn[i]*8);
                cp16(sbb + lrow[i]*PITCHB + lchn[i]*16,
                     B + (size_t)(bn + lrow[i]) * K + t * KSLAB + lchn[i]*8);
            }
        }
        CP_COMMIT();

        uint32_t Asm = sb + (slab % GS) * PAIR_B;
        uint32_t Bsm = Asm + STAGE_B;
        #pragma unroll
        for (int kt = 0; kt < 4; kt++) {
            uint32_t af[4][4];
            #pragma unroll
            for (int mt = 0; mt < 4; mt++)
                ldsm4(af[mt][0], af[mt][1], af[mt][2], af[mt][3],
                      Asm + aoffs + mt * (16 * PITCHB) + kt * 32);
            uint32_t bf[4][2];
            #pragma unroll
            for (int p = 0; p < 2; p++) {
                uint32_t r0, r1, r2, r3;
                ldsm4(r0, r1, r2, r3,
                      Bsm + boffs + p * (16 * PITCHB) + kt * 32);
                bf[p*2][0]   = r0; bf[p*2][1]   = r1;
                bf[p*2+1][0] = r2; bf[p*2+1][1] = r3;
            }
            #pragma unroll
            for (int mt = 0; mt < 4; mt++)
                #pragma unroll
                for (int nt = 0; nt < 4; nt++)
                    mma_f16(acc[mt][nt], af[mt][0], af[mt][1], af[mt][2], af[mt][3],
                            bf[nt][0], bf[nt][1]);
        }
    }

    #pragma unroll
    for (int mt = 0; mt < 4; mt++) {
        #pragma unroll
        for (int nt = 0; nt < 4; nt++) {
            int r0o = bm + warp_m + mt * 16 + tg;
            int r1o = r0o + 8;
            int c = bn + warp_n + nt * 8 + tq * 2;
            float2 v0 = make_float2(acc[mt][nt][0], acc[mt][nt][1]);
            float2 v1 = make_float2(acc[mt][nt][2], acc[mt][nt][3]);
            if (EPI == 1) {
                float* Cf = (float*)Cout;
                float2 rv0 = *(const float2*)(R + (size_t)r0o * N + c);
                float2 rv1 = *(const float2*)(R + (size_t)r1o * N + c);
                v0.x += rv0.x; v0.y += rv0.y;
                v1.x += rv1.x; v1.y += rv1.y;
                *(float2*)(Cf + (size_t)r0o * N + c) = v0;
                *(float2*)(Cf + (size_t)r1o * N + c) = v1;
            } else {
                if (EPI == 2) {
                    v0.x = gelu_erf(v0.x); v0.y = gelu_erf(v0.y);
                    v1.x = gelu_erf(v1.x); v1.y = gelu_erf(v1.y);
                }
                __half* Ch = (__half*)Cout;
                *(uint32_t*)(Ch + (size_t)r0o * N + c) = pack_h2(v0.x, v0.y);
                *(uint32_t*)(Ch + (size_t)r1o * N + c) = pack_h2(v1.x, v1.y);
            }
        }
    }
}

// ---------------- fp16 flash attention (causal, dk=64, log2-softmax, cp.async) ----------------
#define FPH   72
#define FPHB  (FPH*2)           // 144
#define QBYTES (64*FPHB)        // 9216
#define KVPAIR (2*QBYTES)       // 18432 per stage
#define FSMH  (QBYTES + 2*KVPAIR)   // 46080
#define QSCAL 0.18033688011112042f  // 0.125 * log2(e)

__global__ void __launch_bounds__(128)
flash_h(const __half* __restrict__ q, const __half* __restrict__ k,
        const __half* __restrict__ v, __half* __restrict__ o, int ldq) {
    extern __shared__ __align__(16) char smc[];
    uint32_t sbase = smem_u32(smc);
    __half* Qh = (__half*)smc;

    int qi = blockIdx.x;
    int bh = blockIdx.y;
    int b = bh >> 4, h = bh & 15;
    const __half* qp    = q + ((size_t)(b*SS + qi*64)) * ldq + h*DKH;
    const __half* kbase = k + (size_t)b * SS * ldq + h*DKH;
    const __half* vbase = v + (size_t)b * SS * ldq + h*DKH;

    int tid = threadIdx.x;
    int w = tid >> 5, lane = tid & 31;
    int tg = lane >> 2, tq = lane & 3;
    int li = lane & 7, ls = lane >> 3;

    int lr = tid >> 2, lch = tid & 3;

    uint32_t aoffs = (uint32_t)((w*16 + li + (ls & 1) * 8) * FPHB + (ls >> 1) * 16);
    uint32_t boffs = (uint32_t)((li + (ls >> 1) * 8) * FPHB + (ls & 1) * 16);
    uint32_t voffs = (uint32_t)((li + (ls & 1) * 8) * FPHB + (ls >> 1) * 16);

    #pragma unroll
    for (int i = 0; i < 2; i++) {
        int r = lr + i * 32;
        #pragma unroll
        for (int jc = 0; jc < 2; jc++) {
            int c = (lch + jc * 4) * 8;
            const __half2* qg = (const __half2*)(qp + (size_t)r * ldq + c);
            uint32_t* qs = (uint32_t*)(Qh + r * FPH + c);
            #pragma unroll
            for (int j = 0; j < 4; j++) {
                float2 f = __half22float2(qg[j]);
                qs[j] = pack_h2(f.x * QSCAL, f.y * QSCAL);
            }
        }
    }
    __syncthreads();
    uint32_t qf[4][4];
    #pragma unroll
    for (int kt = 0; kt < 4; kt++)
        ldsm4(qf[kt][0], qf[kt][1], qf[kt][2], qf[kt][3], sbase + aoffs + kt * 32);

    {
        uint32_t Ks0 = sbase + QBYTES;
        uint32_t Vs0 = Ks0 + QBYTES;
        #pragma unroll
        for (int i = 0; i < 2; i++) {
            int r = lr + i * 32;
            #pragma unroll
            for (int jc = 0; jc < 2; jc++) {
                int c = lch + jc * 4;
                cp16(Ks0 + r*FPHB + c*16, kbase + (size_t)r * ldq + c*8);
                cp16(Vs0 + r*FPHB + c*16, vbase + (size_t)r * ldq + c*8);
            }
        }
        CP_COMMIT();
    }

    float ofrag[8][4];
    #pragma unroll
    for (int nt = 0; nt < 8; nt++)
        #pragma unroll
        for (int j = 0; j < 4; j++) ofrag[nt][j] = 0.f;
    float mrow0 = -INFINITY, mrow1 = -INFINITY, lrow0 = 0.f, lrow1 = 0.f;
    const uint32_t ONE2 = 0x3C003C00u;

    for (int jt = 0; jt <= qi; jt++) {
        __syncthreads();
        if (jt < qi) {
            int nt_ = jt + 1;
            uint32_t Ksn = sbase + QBYTES + ((nt_) & 1) * KVPAIR;
            uint32_t Vsn = Ksn + QBYTES;
            #pragma unroll
            for (int i = 0; i < 2; i++) {
                int r = lr + i * 32;
                #pragma unroll
                for (int jc = 0; jc < 2; jc++) {
                    int c = lch + jc * 4;
                    cp16(Ksn + r*FPHB + c*16, kbase + (size_t)(nt_*64 + r) * ldq + c*8);
                    cp16(Vsn + r*FPHB + c*16, vbase + (size_t)(nt_*64 + r) * ldq + c*8);
                }
            }
            CP_COMMIT();
            asm volatile("cp.async.wait_group 1;" ::: "memory");
        } else {
            asm volatile("cp.async.wait_group 0;" ::: "memory");
        }
        __syncthreads();

        uint32_t Ksm = sbase + QBYTES + (jt & 1) * KVPAIR;
        uint32_t Vsm = Ksm + QBYTES;

        float s[8][4];
        #pragma unroll
        for (int nt = 0; nt < 8; nt++)
            #pragma unroll
            for (int j = 0; j < 4; j++) s[nt][j] = 0.f;
        #pragma unroll
        for (int kt = 0; kt < 4; kt++) {
            #pragma unroll
            for (int nb = 0; nb < 4; nb++) {
                uint32_t r0, r1, r2, r3;
                ldsm4(r0, r1, r2, r3, Ksm + boffs + nb * (16 * FPHB) + kt * 32);
                mma_f16(s[nb*2],   qf[kt][0], qf[kt][1], qf[kt][2], qf[kt][3], r0, r1);
                mma_f16(s[nb*2+1], qf[kt][0], qf[kt][1], qf[kt][2], qf[kt][3], r2, r3);
            }
        }

        if (jt == qi) {
            int r0 = w*16 + tg, r1 = r0 + 8;
            #pragma unroll
            for (int nt = 0; nt < 8; nt++) {
                int c0 = nt*8 + 2*tq, c1 = c0 + 1;
                if (c0 > r0) s[nt][0] = -INFINITY;
                if (c1 > r0) s[nt][1] = -INFINITY;
                if (c0 > r1) s[nt][2] = -INFINITY;
                if (c1 > r1) s[nt][3] = -INFINITY;
            }
        }

        float m0 = -INFINITY, m1 = -INFINITY;
        #pragma unroll
        for (int nt = 0; nt < 8; nt++) {
            m0 = fmaxf(m0, fmaxf(s[nt][0], s[nt][1]));
            m1 = fmaxf(m1, fmaxf(s[nt][2], s[nt][3]));
        }
        m0 = fmaxf(m0, __shfl_xor_sync(0xffffffffu, m0, 1));
        m0 = fmaxf(m0, __shfl_xor_sync(0xffffffffu, m0, 2));
        m1 = fmaxf(m1, __shfl_xor_sync(0xffffffffu, m1, 1));
        m1 = fmaxf(m1, __shfl_xor_sync(0xffffffffu, m1, 2));

        float mn0 = fmaxf(mrow0, m0), mn1 = fmaxf(mrow1, m1);
        float corr0 = ex2f(mrow0 - mn0), corr1 = ex2f(mrow1 - mn1);
        mrow0 = mn0; mrow1 = mn1;

        uint32_t pk[4][4];
        #pragma unroll
        for (int nt = 0; nt < 8; nt++) {
            int kt = nt >> 1, hi = nt & 1;
            pk[kt][hi*2]     = ex2_h2(pack_h2(s[nt][0] - mn0, s[nt][1] - mn0));
            pk[kt][hi*2 + 1] = ex2_h2(pack_h2(s[nt][2] - mn1, s[nt][3] - mn1));
            ofrag[nt][0] *= corr0; ofrag[nt][1] *= corr0;
            ofrag[nt][2] *= corr1; ofrag[nt][3] *= corr1;
        }

        float rsf[4] = {0.f, 0.f, 0.f, 0.f};
        #pragma unroll
        for (int kt = 0; kt < 4; kt++)
            mma_f16(rsf, pk[kt][0], pk[kt][1], pk[kt][2], pk[kt][3], ONE2, ONE2);
        lrow0 = lrow0 * corr0 + rsf[0];
        lrow1 = lrow1 * corr1 + rsf[2];

        #pragma unroll
        for (int kt = 0; kt < 4; kt++) {
            #pragma unroll
            for (int nb = 0; nb < 4; nb++) {
                uint32_t r0, r1, r2, r3;
                ldsm4t(r0, r1, r2, r3,
                       Vsm + voffs + kt * (16 * FPHB) + nb * 32);
                mma_f16(ofrag[nb*2],   pk[kt][0], pk[kt][1], pk[kt][2], pk[kt][3], r0, r1);
                mma_f16(ofrag[nb*2+1], pk[kt][0], pk[kt][1], pk[kt][2], pk[kt][3], r2, r3);
            }
        }
    }

    float inv0 = 1.0f / lrow0, inv1 = 1.0f / lrow1;
    int r0 = qi*64 + w*16 + tg, r1 = r0 + 8;
    __half* op = o + (size_t)(b*SS) * DD + h*DKH;
    #pragma unroll
    for (int nt = 0; nt < 8; nt++) {
        int c = nt*8 + 2*tq;
        *(uint32_t*)(op + (size_t)r0 * DD + c) =
            pack_h2(ofrag[nt][0]*inv0, ofrag[nt][1]*inv0);
        *(uint32_t*)(op + (size_t)r1 * DD + c) =
            pack_h2(ofrag[nt][2]*inv1, ofrag[nt][3]*inv1);
    }
}

// ---------------- launch ----------------
extern "C" void kernel_launch(void* const* d_in, const int* in_sizes, int n_in,
                              void* d_out, int out_size) {
    const float* x  = (const float*)d_in[0];
    const float* g1 = (const float*)d_in[1];
    const float* g2 = (const float*)d_in[2];
    const float* wq = (const float*)d_in[3];
    const float* wk = (const float*)d_in[4];
    const float* wv = (const float*)d_in[5];
    const float* wo = (const float*)d_in[6];
    const float* w1 = (const float*)d_in[7];
    const float* w2 = (const float*)d_in[8];
    float* out = (float*)d_out;

    __half *xn, *qkv, *att, *xn2, *ff, *wqkvc, *woc, *w1c, *w2c;
    float* x1;
    cudaGetSymbolAddress((void**)&xn,    g_xn);
    cudaGetSymbolAddress((void**)&qkv,   g_qkv);
    cudaGetSymbolAddress((void**)&att,   g_att);
    cudaGetSymbolAddress((void**)&x1,    g_x1);
    cudaGetSymbolAddress((void**)&xn2,   g_xn2);
    cudaGetSymbolAddress((void**)&ff,    g_ff);
    cudaGetSymbolAddress((void**)&wqkvc, g_wqkv);
    cudaGetSymbolAddress((void**)&woc,   g_woc);
    cudaGetSymbolAddress((void**)&w1c,   g_w1c);
    cudaGetSymbolAddress((void**)&w2c,   g_w2c);

    cudaFuncSetAttribute(flash_h,
                         cudaFuncAttributeMaxDynamicSharedMemorySize, FSMH);
    cudaFuncSetAttribute(gemm_h<0>,
                         cudaFuncAttributeMaxDynamicSharedMemorySize, GSMEM);
    cudaFuncSetAttribute(gemm_h<1>,
                         cudaFuncAttributeMaxDynamicSharedMemorySize, GSMEM);
    cudaFuncSetAttribute(gemm_h<2>,
                         cudaFuncAttributeMaxDynamicSharedMemorySize, GSMEM);

    cvt_all<<<1024, 256>>>(wq, wk, wv, wo, w1, w2, wqkvc, woc, w1c, w2c);

    // 1. xn = rmsnorm(x, g1)  (warp-per-row)
    rmsnorm_kernel<<<MM/8, 256>>>(x, g1, xn);
    // 2. fused QKV
    gemm_h<0><<<dim3(3*DD/128, MM/128), 256, GSMEM>>>(xn, wqkvc, nullptr, qkv,
                                                      MM, 3*DD, DD);
    // 3. causal flash attention
    flash_h<<<dim3(SS/64, BB*HH), 128, FSMH>>>(qkv, qkv + DD, qkv + 2*DD, att, 3*DD);
    // 4. x1 = x + att @ wo^T
    gemm_h<1><<<dim3(DD/128, MM/128), 256, GSMEM>>>(att, woc, x, x1, MM, DD, DD);
    // 5. xn2 = rmsnorm(x1, g2)
    rmsnorm_kernel<<<MM/8, 256>>>(x1, g2, xn2);
    // 6. ff = gelu(xn2 @ w1^T)
    gemm_h<2><<<dim3(DFF/128, MM/128), 256, GSMEM>>>(xn2, w1c, nullptr, ff,
                                                     MM, DFF, DD);
    // 7. out = x1 + ff @ w2^T
    gemm_h<1><<<dim3(DD/128, MM/128), 256, GSMEM>>>(ff, w2c, x1, out, MM, DD, DFF);
}